// round 1
// baseline (speedup 1.0000x reference)
#include <cuda_runtime.h>
#include <float.h>

// Problem constants
#define B_   16
#define N_   2048
#define C_   128
#define M_   (B_ * N_)          // 32768 rows
#define KNN  8
#define NBLK 4

#define ALPHA_F    0.8888888888888888f   // 8/9
#define ONEMA_F    0.1111111111111111f   // 1/9
#define WEDGE_F    0.125f                // normalized adjacency entry (deg=8 everywhere)

// ---------------- scratch (static device globals; no allocs allowed) ---------
__device__ float g_pts[M_ * C_];
__device__ float g_Yc [M_ * C_];
__device__ float g_Yg [M_ * C_];
__device__ float g_Uc [M_ * 6];
__device__ float g_Ug [M_ * 6];
__device__ int   g_nbr[M_ * KNN];   // [0]=self, [1..7]=kNN (within-batch indices)

// ---------------- 1) kNN top-8 (smallest dist, stable ties) ------------------
__global__ void knn_kernel(const float* __restrict__ xyz) {
    __shared__ float sx[N_], sy[N_], sz[N_], s2[N_];
    int b = blockIdx.x >> 3;
    int qBase = (blockIdx.x & 7) * 256;
    const float* X = xyz + (size_t)b * 3 * N_;
    for (int i = threadIdx.x; i < N_; i += 256) {
        float x = X[i], y = X[N_ + i], z = X[2 * N_ + i];
        sx[i] = x; sy[i] = y; sz[i] = z;
        s2[i] = x * x + y * y + z * z;   // same op order as jnp.sum(xyz*xyz, axis=1)
    }
    __syncthreads();

    int q = qBase + threadIdx.x;
    float qx = sx[q], qy = sy[q], qz = sz[q], q2 = s2[q];
    float bd[KNN]; int bi[KNN];
#pragma unroll
    for (int s = 0; s < KNN; ++s) { bd[s] = FLT_MAX; bi[s] = 0x7fffffff; }

    for (int j = 0; j < N_; ++j) {
        float inner = qx * sx[j] + qy * sy[j] + qz * sz[j];
        float d = (q2 + s2[j]) - 2.0f * inner;   // matches x2i + x2j - 2*inner
        if (d < bd[KNN - 1]) {                   // strict <: stable tie (lower idx wins)
            bd[KNN - 1] = d; bi[KNN - 1] = j;
#pragma unroll
            for (int s = KNN - 1; s > 0; --s) {
                if (bd[s] < bd[s - 1]) {
                    float td = bd[s]; bd[s] = bd[s - 1]; bd[s - 1] = td;
                    int   ti = bi[s]; bi[s] = bi[s - 1]; bi[s - 1] = ti;
                }
            }
        }
    }
    int* outp = g_nbr + (size_t)(b * N_ + q) * KNN;
    outp[0] = q;                       // self-loop (reference forces diag = 1)
#pragma unroll
    for (int s = 1; s < KNN; ++s) outp[s] = bi[s];   // ref drops idx[...,0]
}

// ---------------- 2) transpose points (B,C,N) -> pts (B,N,C) -----------------
__global__ void transpose_in(const float* __restrict__ pin) {
    __shared__ float tile[32][33];
    int b = blockIdx.z;
    int n0 = blockIdx.x * 32, c0 = blockIdx.y * 32;
    const float* src = pin + (size_t)b * C_ * N_;
    float* dst = g_pts + (size_t)b * N_ * C_;
    for (int r = threadIdx.y; r < 32; r += 8)
        tile[r][threadIdx.x] = src[(c0 + r) * N_ + n0 + threadIdx.x];
    __syncthreads();
    for (int r = threadIdx.y; r < 32; r += 8)
        dst[(n0 + r) * C_ + c0 + threadIdx.x] = tile[threadIdx.x][r];
}

// ---------------- 3) dual-output SGEMM: Yc = relu(A)@WcT, Yg = A@WgT ---------
// A: (M_,128) row-major; W: (128 d, 128 c) row-major (reduce over c) -> "NT" gemm.
// BM=64 rows/block, BN=128 (all cols), BK=16. 256 threads, each 4x8 outputs x2.
#define BM 64
#define BK 16
__global__ __launch_bounds__(256) void gemm_dual(const float* __restrict__ Wc,
                                                 const float* __restrict__ Wg) {
    __shared__ float sA [BK][BM];
    __shared__ float sWc[BK][C_];
    __shared__ float sWg[BK][C_];
    const float* A = g_pts;
    int tid = threadIdx.x;
    int tx = tid & 15;          // col group: cols tx*8 .. tx*8+7
    int ty = tid >> 4;          // row group: rows ty*4 .. ty*4+3
    int row0 = blockIdx.x * BM;

    float accC[4][8], accG[4][8];
#pragma unroll
    for (int i = 0; i < 4; ++i)
#pragma unroll
        for (int j = 0; j < 8; ++j) { accC[i][j] = 0.f; accG[i][j] = 0.f; }

    for (int k0 = 0; k0 < C_; k0 += BK) {
        // A tile: 64x16 = 256 float4 loads (1 per thread)
        {
            int m = tid >> 2;
            int kq = (tid & 3) * 4;
            float4 v = *(const float4*)&A[(size_t)(row0 + m) * C_ + k0 + kq];
            sA[kq + 0][m] = v.x; sA[kq + 1][m] = v.y;
            sA[kq + 2][m] = v.z; sA[kq + 3][m] = v.w;
        }
        // W tiles: 128x16 each = 512 float4 -> 2 per thread per matrix
#pragma unroll
        for (int r = 0; r < 2; ++r) {
            int idx = tid + r * 256;
            int d = idx >> 2;
            int kq = (idx & 3) * 4;
            float4 vc = *(const float4*)&Wc[d * C_ + k0 + kq];
            sWc[kq + 0][d] = vc.x; sWc[kq + 1][d] = vc.y;
            sWc[kq + 2][d] = vc.z; sWc[kq + 3][d] = vc.w;
            float4 vg = *(const float4*)&Wg[d * C_ + k0 + kq];
            sWg[kq + 0][d] = vg.x; sWg[kq + 1][d] = vg.y;
            sWg[kq + 2][d] = vg.z; sWg[kq + 3][d] = vg.w;
        }
        __syncthreads();
#pragma unroll
        for (int kk = 0; kk < BK; ++kk) {
            float4 av = *(const float4*)&sA[kk][ty * 4];
            float a[4]  = {av.x, av.y, av.z, av.w};
            float ar[4] = {fmaxf(av.x, 0.f), fmaxf(av.y, 0.f),
                           fmaxf(av.z, 0.f), fmaxf(av.w, 0.f)};
            float4 wc0 = *(const float4*)&sWc[kk][tx * 8];
            float4 wc1 = *(const float4*)&sWc[kk][tx * 8 + 4];
            float4 wg0 = *(const float4*)&sWg[kk][tx * 8];
            float4 wg1 = *(const float4*)&sWg[kk][tx * 8 + 4];
            float wc[8] = {wc0.x, wc0.y, wc0.z, wc0.w, wc1.x, wc1.y, wc1.z, wc1.w};
            float wg[8] = {wg0.x, wg0.y, wg0.z, wg0.w, wg1.x, wg1.y, wg1.z, wg1.w};
#pragma unroll
            for (int i = 0; i < 4; ++i)
#pragma unroll
                for (int j = 0; j < 8; ++j) {
                    accC[i][j] += ar[i] * wc[j];
                    accG[i][j] += a[i]  * wg[j];
                }
        }
        __syncthreads();
    }
#pragma unroll
    for (int i = 0; i < 4; ++i) {
        int r = row0 + ty * 4 + i;
#pragma unroll
        for (int j = 0; j < 8; j += 4) {
            int d = tx * 8 + j;
            *(float4*)&g_Yc[(size_t)r * C_ + d] =
                make_float4(accC[i][j], accC[i][j+1], accC[i][j+2], accC[i][j+3]);
            *(float4*)&g_Yg[(size_t)r * C_ + d] =
                make_float4(accG[i][j], accG[i][j+1], accG[i][j+2], accG[i][j+3]);
        }
    }
}

// ------- 4) gather + residual: pts = pts + a*Yc + (1-a)*(adj@Yg) -------------
// one warp per node, float4 over 128 channels
__global__ void gather_combine() {
    int node = blockIdx.x * 8 + (threadIdx.x >> 5);
    int lane = threadIdx.x & 31;
    int base = node & ~(N_ - 1);                  // batch start row
    const int* nb = g_nbr + (size_t)node * KNN;
    int c = lane * 4;
    float4 acc = make_float4(0.f, 0.f, 0.f, 0.f);
#pragma unroll
    for (int s = 0; s < KNN; ++s) {
        const float4 v = *(const float4*)&g_Yg[(size_t)(base + nb[s]) * C_ + c];
        acc.x += v.x; acc.y += v.y; acc.z += v.z; acc.w += v.w;
    }
    float4 yc = *(const float4*)&g_Yc[(size_t)node * C_ + c];
    float4 p  = *(const float4*)&g_pts[(size_t)node * C_ + c];
    float4 o;
    o.x = p.x + ALPHA_F * yc.x + ONEMA_F * (WEDGE_F * acc.x);
    o.y = p.y + ALPHA_F * yc.y + ONEMA_F * (WEDGE_F * acc.y);
    o.z = p.z + ALPHA_F * yc.z + ONEMA_F * (WEDGE_F * acc.z);
    o.w = p.w + ALPHA_F * yc.w + ONEMA_F * (WEDGE_F * acc.w);
    *(float4*)&g_pts[(size_t)node * C_ + c] = o;
}

// ------- 5) unpool projection: Uc = pts@WucT, Ug = pts@WugT (6 outs each) ----
__global__ void unpool_proj(const float* __restrict__ Wuc,
                            const float* __restrict__ Wug) {
    __shared__ float swc[6 * C_], swg[6 * C_];
    for (int i = threadIdx.x; i < 6 * C_; i += 256) { swc[i] = Wuc[i]; swg[i] = Wug[i]; }
    __syncthreads();
    int node = blockIdx.x * 8 + (threadIdx.x >> 5);
    int lane = threadIdx.x & 31;
    float4 p = *(const float4*)&g_pts[(size_t)node * C_ + lane * 4];
#pragma unroll
    for (int o = 0; o < 6; ++o) {
        float4 wc = *(const float4*)&swc[o * C_ + lane * 4];
        float4 wg = *(const float4*)&swg[o * C_ + lane * 4];
        float dc = p.x * wc.x + p.y * wc.y + p.z * wc.z + p.w * wc.w;
        float dg = p.x * wg.x + p.y * wg.y + p.z * wg.z + p.w * wg.w;
#pragma unroll
        for (int off = 16; off; off >>= 1) {
            dc += __shfl_xor_sync(0xffffffffu, dc, off);
            dg += __shfl_xor_sync(0xffffffffu, dg, off);
        }
        if (lane == 0) {
            g_Uc[(size_t)node * 6 + o] = dc;
            g_Ug[(size_t)node * 6 + o] = dg;
        }
    }
}

// ------- 6) finalize new_xyz: a*Uc + (1-a)*(adj@Ug), fold + reshape ----------
__global__ void finalize_xyz(const float* __restrict__ xyz, float* __restrict__ out) {
    int node = blockIdx.x * 256 + threadIdx.x;        // 0..32767
    int b = node >> 11, n = node & (N_ - 1);
    int base = node & ~(N_ - 1);
    const int* nb = g_nbr + (size_t)node * KNN;
    float g[6] = {0.f, 0.f, 0.f, 0.f, 0.f, 0.f};
#pragma unroll
    for (int s = 0; s < KNN; ++s) {
        const float* r = g_Ug + (size_t)(base + nb[s]) * 6;
#pragma unroll
        for (int o = 0; o < 6; ++o) g[o] += r[o];
    }
#pragma unroll
    for (int o = 0; o < 6; ++o) {
        float v = ALPHA_F * g_Uc[(size_t)node * 6 + o] + ONEMA_F * (WEDGE_F * g[o]);
        int cdim = o >> 1, t = o & 1;
        out[(size_t)b * 3 * (2 * N_) + cdim * (2 * N_) + t * N_ + n] =
            v + xyz[(size_t)b * 3 * N_ + cdim * N_ + n];
    }
}

// ------- 7) transpose pts (B,N,C) -> output (B,C,N) --------------------------
__global__ void transpose_out(float* __restrict__ out) {
    __shared__ float tile[32][33];
    int b = blockIdx.z;
    int n0 = blockIdx.x * 32, c0 = blockIdx.y * 32;
    const float* src = g_pts + (size_t)b * N_ * C_;
    float* dst = out + (size_t)b * C_ * N_;
    for (int r = threadIdx.y; r < 32; r += 8)
        tile[r][threadIdx.x] = src[(n0 + r) * C_ + c0 + threadIdx.x];
    __syncthreads();
    for (int r = threadIdx.y; r < 32; r += 8)
        dst[(c0 + r) * N_ + n0 + threadIdx.x] = tile[threadIdx.x][r];
}

// -----------------------------------------------------------------------------
extern "C" void kernel_launch(void* const* d_in, const int* in_sizes, int n_in,
                              void* d_out, int out_size) {
    const float* xyz    = (const float*)d_in[0];   // (16,3,2048)
    const float* points = (const float*)d_in[1];   // (16,128,2048)
    const float* Wc     = (const float*)d_in[2];   // (4,128,128)
    const float* Wg     = (const float*)d_in[3];   // (4,128,128)
    const float* Wuc    = (const float*)d_in[4];   // (6,128)
    const float* Wug    = (const float*)d_in[5];   // (6,128)
    float* out = (float*)d_out;                    // [new_xyz | pts_T] concatenated
    (void)in_sizes; (void)n_in; (void)out_size;

    knn_kernel<<<B_ * 8, 256>>>(xyz);
    transpose_in<<<dim3(N_ / 32, C_ / 32, B_), dim3(32, 8)>>>(points);
    for (int i = 0; i < NBLK; ++i) {
        gemm_dual<<<M_ / BM, 256>>>(Wc + (size_t)i * C_ * C_, Wg + (size_t)i * C_ * C_);
        gather_combine<<<M_ / 8, 256>>>();
    }
    unpool_proj<<<M_ / 8, 256>>>(Wuc, Wug);
    finalize_xyz<<<M_ / 256, 256>>>(xyz, out);
    transpose_out<<<dim3(N_ / 32, C_ / 32, B_), dim3(32, 8)>>>(out + (size_t)B_ * 3 * 2 * N_);
}

// round 2
// speedup vs baseline: 1.1229x; 1.1229x over previous
#include <cuda_runtime.h>
#include <float.h>

// Problem constants
#define B_   16
#define N_   2048
#define C_   128
#define M_   (B_ * N_)          // 32768 rows
#define KNN  8
#define NBLK 4

#define ALPHA_F    0.8888888888888888f   // 8/9
#define ONEMA_F    0.1111111111111111f   // 1/9
#define WEDGE_F    0.125f                // normalized adjacency entry (deg=8 everywhere)

typedef unsigned long long u64;

__device__ __forceinline__ void ffma2(u64 &acc, u64 a, u64 b) {
    asm("fma.rn.f32x2 %0, %1, %2, %0;" : "+l"(acc) : "l"(a), "l"(b));
}
__device__ __forceinline__ float2 unpack2(u64 v) {
    float2 f; asm("mov.b64 {%0, %1}, %2;" : "=f"(f.x), "=f"(f.y) : "l"(v)); return f;
}

// ---------------- scratch (static device globals; no allocs allowed) ---------
__device__ float g_pts[M_ * C_];
__device__ float g_Ya [M_ * C_];   // epilogue-fused: pts + alpha * relu(pts)@WcT
__device__ float g_Yg [M_ * C_];
__device__ float g_Uc [M_ * 6];
__device__ float g_Ug [M_ * 6];
__device__ int   g_nbr[M_ * KNN];  // [0]=self, [1..7]=kNN (within-batch indices)

// ---------------- 1) kNN top-8 (smallest dist, stable ties) ------------------
__global__ void knn_kernel(const float* __restrict__ xyz) {
    __shared__ float sx[N_], sy[N_], sz[N_], s2[N_];
    int b = blockIdx.x >> 3;
    int qBase = (blockIdx.x & 7) * 256;
    const float* X = xyz + (size_t)b * 3 * N_;
    for (int i = threadIdx.x; i < N_; i += 256) {
        float x = X[i], y = X[N_ + i], z = X[2 * N_ + i];
        sx[i] = x; sy[i] = y; sz[i] = z;
        s2[i] = x * x + y * y + z * z;
    }
    __syncthreads();

    int q = qBase + threadIdx.x;
    float qx = sx[q], qy = sy[q], qz = sz[q], q2 = s2[q];
    float bd[KNN]; int bi[KNN];
#pragma unroll
    for (int s = 0; s < KNN; ++s) { bd[s] = FLT_MAX; bi[s] = 0x7fffffff; }

    for (int j = 0; j < N_; ++j) {
        float inner = qx * sx[j] + qy * sy[j] + qz * sz[j];
        float d = (q2 + s2[j]) - 2.0f * inner;
        if (d < bd[KNN - 1]) {                   // strict <: stable tie (lower idx wins)
            bd[KNN - 1] = d; bi[KNN - 1] = j;
#pragma unroll
            for (int s = KNN - 1; s > 0; --s) {
                if (bd[s] < bd[s - 1]) {
                    float td = bd[s]; bd[s] = bd[s - 1]; bd[s - 1] = td;
                    int   ti = bi[s]; bi[s] = bi[s - 1]; bi[s - 1] = ti;
                }
            }
        }
    }
    int* outp = g_nbr + (size_t)(b * N_ + q) * KNN;
    outp[0] = q;
#pragma unroll
    for (int s = 1; s < KNN; ++s) outp[s] = bi[s];
}

// ---------------- 2) transpose points (B,C,N) -> pts (B,N,C) -----------------
__global__ void transpose_in(const float* __restrict__ pin) {
    __shared__ float tile[32][33];
    int b = blockIdx.z;
    int n0 = blockIdx.x * 32, c0 = blockIdx.y * 32;
    const float* src = pin + (size_t)b * C_ * N_;
    float* dst = g_pts + (size_t)b * N_ * C_;
    for (int r = threadIdx.y; r < 32; r += 8)
        tile[r][threadIdx.x] = src[(c0 + r) * N_ + n0 + threadIdx.x];
    __syncthreads();
    for (int r = threadIdx.y; r < 32; r += 8)
        dst[(n0 + r) * C_ + c0 + threadIdx.x] = tile[threadIdx.x][r];
}

// ---------------- 3) dual-output SGEMM via packed fma.rn.f32x2 ---------------
//   Ya = pts + ALPHA * (relu(pts) @ WcT)      (residual fused)
//   Yg = pts @ WgT
// BM=128 rows/block, BN=128 (all cols), BK=16, 256 threads.
// Per thread: 8 rows x 8 cols x 2 matrices, accumulators as 64 packed u64.
// A stored in smem pre-duplicated (a,a) and pre-relu'd, so inner-loop operands
// load directly as ulonglong2 with zero packing ALU.
#define BM 128
#define BK 16
__global__ __launch_bounds__(256, 1) void gemm_dual(const float* __restrict__ Wc,
                                                    const float* __restrict__ Wg) {
    __shared__ float2 sA2 [BK][BM];   // (a,a)
    __shared__ float2 sAr2[BK][BM];   // (relu a, relu a)
    __shared__ float  sWc[BK][C_];
    __shared__ float  sWg[BK][C_];
    const float* A = g_pts;
    int tid = threadIdx.x;
    int tx = tid & 15;          // cols tx*8 .. tx*8+7
    int ty = tid >> 4;          // rows ty*8 .. ty*8+7
    int row0 = blockIdx.x * BM;

    u64 accC[8][4], accG[8][4];
#pragma unroll
    for (int i = 0; i < 8; ++i)
#pragma unroll
        for (int j = 0; j < 4; ++j) { accC[i][j] = 0ull; accG[i][j] = 0ull; }

    for (int k0 = 0; k0 < C_; k0 += BK) {
        // A tile: 128x16 = 512 float4 -> 2 per thread (duplicated + relu'd)
#pragma unroll
        for (int r = 0; r < 2; ++r) {
            int idx = tid + r * 256;
            int m = idx >> 2;
            int kq = (idx & 3) * 4;
            float4 v = *(const float4*)&A[(size_t)(row0 + m) * C_ + k0 + kq];
            sA2 [kq + 0][m] = make_float2(v.x, v.x);
            sA2 [kq + 1][m] = make_float2(v.y, v.y);
            sA2 [kq + 2][m] = make_float2(v.z, v.z);
            sA2 [kq + 3][m] = make_float2(v.w, v.w);
            float rx = fmaxf(v.x, 0.f), ry = fmaxf(v.y, 0.f);
            float rz = fmaxf(v.z, 0.f), rw = fmaxf(v.w, 0.f);
            sAr2[kq + 0][m] = make_float2(rx, rx);
            sAr2[kq + 1][m] = make_float2(ry, ry);
            sAr2[kq + 2][m] = make_float2(rz, rz);
            sAr2[kq + 3][m] = make_float2(rw, rw);
        }
        // W tiles: 128x16 each = 512 float4 -> 2 per thread per matrix
#pragma unroll
        for (int r = 0; r < 2; ++r) {
            int idx = tid + r * 256;
            int d = idx >> 2;
            int kq = (idx & 3) * 4;
            float4 vc = *(const float4*)&Wc[d * C_ + k0 + kq];
            sWc[kq + 0][d] = vc.x; sWc[kq + 1][d] = vc.y;
            sWc[kq + 2][d] = vc.z; sWc[kq + 3][d] = vc.w;
            float4 vg = *(const float4*)&Wg[d * C_ + k0 + kq];
            sWg[kq + 0][d] = vg.x; sWg[kq + 1][d] = vg.y;
            sWg[kq + 2][d] = vg.z; sWg[kq + 3][d] = vg.w;
        }
        __syncthreads();
#pragma unroll
        for (int kk = 0; kk < BK; ++kk) {
            ulonglong2 a01 = *(const ulonglong2*)&sA2 [kk][ty * 8 + 0];
            ulonglong2 a23 = *(const ulonglong2*)&sA2 [kk][ty * 8 + 2];
            ulonglong2 a45 = *(const ulonglong2*)&sA2 [kk][ty * 8 + 4];
            ulonglong2 a67 = *(const ulonglong2*)&sA2 [kk][ty * 8 + 6];
            ulonglong2 r01 = *(const ulonglong2*)&sAr2[kk][ty * 8 + 0];
            ulonglong2 r23 = *(const ulonglong2*)&sAr2[kk][ty * 8 + 2];
            ulonglong2 r45 = *(const ulonglong2*)&sAr2[kk][ty * 8 + 4];
            ulonglong2 r67 = *(const ulonglong2*)&sAr2[kk][ty * 8 + 6];
            u64 ap[8] = {a01.x, a01.y, a23.x, a23.y, a45.x, a45.y, a67.x, a67.y};
            u64 rp[8] = {r01.x, r01.y, r23.x, r23.y, r45.x, r45.y, r67.x, r67.y};
            ulonglong2 wcq0 = *(const ulonglong2*)&sWc[kk][tx * 8 + 0];
            ulonglong2 wcq1 = *(const ulonglong2*)&sWc[kk][tx * 8 + 4];
            ulonglong2 wgq0 = *(const ulonglong2*)&sWg[kk][tx * 8 + 0];
            ulonglong2 wgq1 = *(const ulonglong2*)&sWg[kk][tx * 8 + 4];
            u64 wc[4] = {wcq0.x, wcq0.y, wcq1.x, wcq1.y};
            u64 wg[4] = {wgq0.x, wgq0.y, wgq1.x, wgq1.y};
#pragma unroll
            for (int i = 0; i < 8; ++i)
#pragma unroll
                for (int j = 0; j < 4; ++j) {
                    ffma2(accC[i][j], rp[i], wc[j]);
                    ffma2(accG[i][j], ap[i], wg[j]);
                }
        }
        __syncthreads();
    }
    // epilogue: Ya = pts + ALPHA*accC ; Yg = accG
#pragma unroll
    for (int i = 0; i < 8; ++i) {
        int r = row0 + ty * 8 + i;
        size_t base = (size_t)r * C_ + tx * 8;
        float4 p0 = *(const float4*)&g_pts[base];
        float4 p1 = *(const float4*)&g_pts[base + 4];
        float2 c0 = unpack2(accC[i][0]), c1 = unpack2(accC[i][1]);
        float2 c2 = unpack2(accC[i][2]), c3 = unpack2(accC[i][3]);
        *(float4*)&g_Ya[base] = make_float4(p0.x + ALPHA_F * c0.x, p0.y + ALPHA_F * c0.y,
                                            p0.z + ALPHA_F * c1.x, p0.w + ALPHA_F * c1.y);
        *(float4*)&g_Ya[base + 4] = make_float4(p1.x + ALPHA_F * c2.x, p1.y + ALPHA_F * c2.y,
                                                p1.z + ALPHA_F * c3.x, p1.w + ALPHA_F * c3.y);
        float2 gg0 = unpack2(accG[i][0]), gg1 = unpack2(accG[i][1]);
        float2 gg2 = unpack2(accG[i][2]), gg3 = unpack2(accG[i][3]);
        *(float4*)&g_Yg[base]     = make_float4(gg0.x, gg0.y, gg1.x, gg1.y);
        *(float4*)&g_Yg[base + 4] = make_float4(gg2.x, gg2.y, gg3.x, gg3.y);
    }
}

// ------- 4) gather + residual: pts = Ya + (1-a)*(adj@Yg) ---------------------
__global__ void gather_combine() {
    int node = blockIdx.x * 8 + (threadIdx.x >> 5);
    int lane = threadIdx.x & 31;
    int base = node & ~(N_ - 1);                  // batch start row
    const int* nb = g_nbr + (size_t)node * KNN;
    int c = lane * 4;
    float4 acc = make_float4(0.f, 0.f, 0.f, 0.f);
#pragma unroll
    for (int s = 0; s < KNN; ++s) {
        const float4 v = *(const float4*)&g_Yg[(size_t)(base + nb[s]) * C_ + c];
        acc.x += v.x; acc.y += v.y; acc.z += v.z; acc.w += v.w;
    }
    float4 ya = *(const float4*)&g_Ya[(size_t)node * C_ + c];
    float4 o;
    o.x = ya.x + ONEMA_F * (WEDGE_F * acc.x);
    o.y = ya.y + ONEMA_F * (WEDGE_F * acc.y);
    o.z = ya.z + ONEMA_F * (WEDGE_F * acc.z);
    o.w = ya.w + ONEMA_F * (WEDGE_F * acc.w);
    *(float4*)&g_pts[(size_t)node * C_ + c] = o;
}

// ------- 5) unpool projection: Uc = pts@WucT, Ug = pts@WugT (6 outs each) ----
__global__ void unpool_proj(const float* __restrict__ Wuc,
                            const float* __restrict__ Wug) {
    __shared__ float swc[6 * C_], swg[6 * C_];
    for (int i = threadIdx.x; i < 6 * C_; i += 256) { swc[i] = Wuc[i]; swg[i] = Wug[i]; }
    __syncthreads();
    int node = blockIdx.x * 8 + (threadIdx.x >> 5);
    int lane = threadIdx.x & 31;
    float4 p = *(const float4*)&g_pts[(size_t)node * C_ + lane * 4];
#pragma unroll
    for (int o = 0; o < 6; ++o) {
        float4 wc = *(const float4*)&swc[o * C_ + lane * 4];
        float4 wg = *(const float4*)&swg[o * C_ + lane * 4];
        float dc = p.x * wc.x + p.y * wc.y + p.z * wc.z + p.w * wc.w;
        float dg = p.x * wg.x + p.y * wg.y + p.z * wg.z + p.w * wg.w;
#pragma unroll
        for (int off = 16; off; off >>= 1) {
            dc += __shfl_xor_sync(0xffffffffu, dc, off);
            dg += __shfl_xor_sync(0xffffffffu, dg, off);
        }
        if (lane == 0) {
            g_Uc[(size_t)node * 6 + o] = dc;
            g_Ug[(size_t)node * 6 + o] = dg;
        }
    }
}

// ------- 6) finalize new_xyz: a*Uc + (1-a)*(adj@Ug), fold + reshape ----------
__global__ void finalize_xyz(const float* __restrict__ xyz, float* __restrict__ out) {
    int node = blockIdx.x * 256 + threadIdx.x;        // 0..32767
    int b = node >> 11, n = node & (N_ - 1);
    int base = node & ~(N_ - 1);
    const int* nb = g_nbr + (size_t)node * KNN;
    float g[6] = {0.f, 0.f, 0.f, 0.f, 0.f, 0.f};
#pragma unroll
    for (int s = 0; s < KNN; ++s) {
        const float* r = g_Ug + (size_t)(base + nb[s]) * 6;
#pragma unroll
        for (int o = 0; o < 6; ++o) g[o] += r[o];
    }
#pragma unroll
    for (int o = 0; o < 6; ++o) {
        float v = ALPHA_F * g_Uc[(size_t)node * 6 + o] + ONEMA_F * (WEDGE_F * g[o]);
        int cdim = o >> 1, t = o & 1;
        out[(size_t)b * 3 * (2 * N_) + cdim * (2 * N_) + t * N_ + n] =
            v + xyz[(size_t)b * 3 * N_ + cdim * N_ + n];
    }
}

// ------- 7) transpose pts (B,N,C) -> output (B,C,N) --------------------------
__global__ void transpose_out(float* __restrict__ out) {
    __shared__ float tile[32][33];
    int b = blockIdx.z;
    int n0 = blockIdx.x * 32, c0 = blockIdx.y * 32;
    const float* src = g_pts + (size_t)b * N_ * C_;
    float* dst = out + (size_t)b * C_ * N_;
    for (int r = threadIdx.y; r < 32; r += 8)
        tile[r][threadIdx.x] = src[(n0 + r) * C_ + c0 + threadIdx.x];
    __syncthreads();
    for (int r = threadIdx.y; r < 32; r += 8)
        dst[(c0 + r) * N_ + n0 + threadIdx.x] = tile[threadIdx.x][r];
}

// -----------------------------------------------------------------------------
extern "C" void kernel_launch(void* const* d_in, const int* in_sizes, int n_in,
                              void* d_out, int out_size) {
    const float* xyz    = (const float*)d_in[0];   // (16,3,2048)
    const float* points = (const float*)d_in[1];   // (16,128,2048)
    const float* Wc     = (const float*)d_in[2];   // (4,128,128)
    const float* Wg     = (const float*)d_in[3];   // (4,128,128)
    const float* Wuc    = (const float*)d_in[4];   // (6,128)
    const float* Wug    = (const float*)d_in[5];   // (6,128)
    float* out = (float*)d_out;                    // [new_xyz | pts_T] concatenated
    (void)in_sizes; (void)n_in; (void)out_size;

    knn_kernel<<<B_ * 8, 256>>>(xyz);
    transpose_in<<<dim3(N_ / 32, C_ / 32, B_), dim3(32, 8)>>>(points);
    for (int i = 0; i < NBLK; ++i) {
        gemm_dual<<<M_ / BM, 256>>>(Wc + (size_t)i * C_ * C_, Wg + (size_t)i * C_ * C_);
        gather_combine<<<M_ / 8, 256>>>();
    }
    unpool_proj<<<M_ / 8, 256>>>(Wuc, Wug);
    finalize_xyz<<<M_ / 256, 256>>>(xyz, out);
    transpose_out<<<dim3(N_ / 32, C_ / 32, B_), dim3(32, 8)>>>(out + (size_t)B_ * 3 * 2 * N_);
}